// round 1
// baseline (speedup 1.0000x reference)
#include <cuda_runtime.h>
#include <math.h>

// Problem constants
#define BG   64
#define NPG  512
#define DEG  32
#define EPG  (NPG*DEG)      // 16384 edges per graph
#define NE   (BG*EPG)       // 1048576
#define NN   (BG*NPG)       // 32768
#define HID  64
#define ACL  16

// ---------------- device scratch (no runtime alloc allowed) ----------------
__device__ int   g_perm[NE];
__device__ int   g_off[NN];
__device__ int   g_cnt[NN];
__device__ float g_pre[NN*64];
__device__ float g_h1[NN*64];
__device__ float g_h2[NN*64];
__device__ float g_sraw[NN*16];
__device__ float g_s[NN*16];
__device__ float g_x1[BG*16*64];
__device__ float g_adj1[BG*16*16];

// ---------------- CSR build: counting sort by dst, per graph ----------------
__global__ void build_csr_k(const int* __restrict__ dst) {
    __shared__ int scnt[NPG];
    __shared__ int soff[NPG];
    int g = blockIdx.x, t = threadIdx.x;
    scnt[t] = 0;
    __syncthreads();
    int ebase = g * EPG, nbase = g * NPG;
    for (int e = t; e < EPG; e += NPG)
        atomicAdd(&scnt[dst[ebase + e] - nbase], 1);
    __syncthreads();
    if (t == 0) {
        int run = 0;
        for (int i = 0; i < NPG; i++) { soff[i] = run; run += scnt[i]; }
    }
    __syncthreads();
    g_off[nbase + t] = ebase + soff[t];
    g_cnt[nbase + t] = scnt[t];
    __syncthreads();
    scnt[t] = soff[t];           // reuse as cursor
    __syncthreads();
    for (int e = t; e < EPG; e += NPG) {
        int d = dst[ebase + e] - nbase;
        int p = atomicAdd(&scnt[d], 1);
        g_perm[ebase + p] = ebase + e;
    }
}

// ---------------- node precompute: out = in @ w[0:K] + b  (w row-major KxF) ----
template<int K, int F>
__global__ void node_pre_k(const float* __restrict__ in, const float* __restrict__ w,
                           const float* __restrict__ b, float* __restrict__ out) {
    __shared__ float sw[K * F];
    __shared__ float sb[F];
    for (int i = threadIdx.x; i < K * F; i += blockDim.x) sw[i] = w[i];
    for (int i = threadIdx.x; i < F;     i += blockDim.x) sb[i] = b[i];
    __syncthreads();
    int idx = blockIdx.x * blockDim.x + threadIdx.x;
    if (idx >= NN * F) return;
    int n = idx / F, f = idx % F;
    const float* row = in + (size_t)n * K;
    float acc = sb[f];
    #pragma unroll 8
    for (int k = 0; k < K; k++) acc = fmaf(row[k], sw[k * F + f], acc);
    out[(size_t)n * F + f] = acc;
}

// ------- fused aggregation: warp per node, per edge relu(pre[src]+ea@w1e),
// ------- sum, then epilogue (R@w2 + cnt*b2)/max(cnt,1) (+optional relu) ------
template<int F, bool RELU>
__global__ void agg_k(const int* __restrict__ src, const float* __restrict__ ea,
                      const float* __restrict__ pre, const float* __restrict__ w1e,
                      const float* __restrict__ w2, const float* __restrict__ b2,
                      float* __restrict__ out) {
    __shared__ float sw1e[8 * F];
    __shared__ float sw2[F * F];
    __shared__ float sb2[F];
    __shared__ float rbuf[8][F];
    for (int i = threadIdx.x; i < 8 * F; i += blockDim.x) sw1e[i] = w1e[i];
    for (int i = threadIdx.x; i < F * F; i += blockDim.x) sw2[i]  = w2[i];
    for (int i = threadIdx.x; i < F;     i += blockDim.x) sb2[i]  = b2[i];
    __syncthreads();
    int warp = threadIdx.x >> 5, lane = threadIdx.x & 31;
    int n = blockIdx.x * 8 + warp;
    int c0 = (F >= 64) ? lane : (lane & (F - 1));
    int c1 = c0 + 32;
    int off = g_off[n], cnt = g_cnt[n];
    float acc0 = 0.f, acc1 = 0.f;
    for (int j = 0; j < cnt; j++) {
        int e = g_perm[off + j];
        int s = src[e];
        float ev = (lane < 8) ? __ldg(ea + (size_t)e * 8 + lane) : 0.f;
        float e0 = __ldg(pre + (size_t)s * F + c0);
        float e1 = 0.f;
        if (F >= 64) e1 = __ldg(pre + (size_t)s * F + c1);
        #pragma unroll
        for (int k = 0; k < 8; k++) {
            float ek = __shfl_sync(0xffffffffu, ev, k);
            e0 = fmaf(ek, sw1e[k * F + c0], e0);
            if (F >= 64) e1 = fmaf(ek, sw1e[k * F + c1], e1);
        }
        acc0 += fmaxf(e0, 0.f);
        if (F >= 64) acc1 += fmaxf(e1, 0.f);
    }
    if (F >= 64 || lane < F) rbuf[warp][c0] = acc0;
    if (F >= 64) rbuf[warp][c1] = acc1;
    __syncwarp();
    float cntf = (float)cnt;
    float cdiv = fmaxf(cntf, 1.f);
    float d0 = cntf * sb2[c0];
    float d1 = (F >= 64) ? cntf * sb2[c1] : 0.f;
    #pragma unroll 8
    for (int k = 0; k < F; k++) {
        float rk = rbuf[warp][k];
        d0 = fmaf(rk, sw2[k * F + c0], d0);
        if (F >= 64) d1 = fmaf(rk, sw2[k * F + c1], d1);
    }
    d0 /= cdiv;
    if (RELU) d0 = fmaxf(d0, 0.f);
    if (F >= 64 || lane < F) out[(size_t)n * F + c0] = d0;
    if (F >= 64) {
        d1 /= cdiv;
        if (RELU) d1 = fmaxf(d1, 0.f);
        out[(size_t)n * F + c1] = d1;
    }
}

// ---------------- double softmax over 16 (reference applies softmax twice) ----
__global__ void softmax2_k(const float* __restrict__ in, float* __restrict__ out) {
    int n = blockIdx.x * blockDim.x + threadIdx.x;
    if (n >= NN) return;
    float v[16];
    #pragma unroll
    for (int i = 0; i < 16; i++) v[i] = in[n * 16 + i];
    #pragma unroll
    for (int pass = 0; pass < 2; pass++) {
        float m = v[0];
        #pragma unroll
        for (int i = 1; i < 16; i++) m = fmaxf(m, v[i]);
        float s = 0.f;
        #pragma unroll
        for (int i = 0; i < 16; i++) { v[i] = expf(v[i] - m); s += v[i]; }
        float inv = 1.f / s;
        #pragma unroll
        for (int i = 0; i < 16; i++) v[i] *= inv;
    }
    #pragma unroll
    for (int i = 0; i < 16; i++) out[n * 16 + i] = v[i];
}

// ---------------- x1[b,c,f] = sum_n s[b,n,c] * h[b,n,f] ----------------
__global__ void x1_k(const float* __restrict__ s, const float* __restrict__ h,
                     float* __restrict__ x1) {
    int g = blockIdx.x, t = threadIdx.x;             // 256 threads
    int f = t & 63, cb = t >> 6;                     // cb in 0..3
    float acc[4] = {0.f, 0.f, 0.f, 0.f};
    const float* sg = s + (size_t)g * NPG * 16;
    const float* hg = h + (size_t)g * NPG * 64;
    for (int n = 0; n < NPG; n++) {
        float hv = hg[n * 64 + f];
        #pragma unroll
        for (int i = 0; i < 4; i++)
            acc[i] = fmaf(sg[n * 16 + cb * 4 + i], hv, acc[i]);
    }
    #pragma unroll
    for (int i = 0; i < 4; i++)
        x1[g * 1024 + (cb * 4 + i) * 64 + f] = acc[i];
}

__global__ void zero_adj_k() {
    int i = blockIdx.x * blockDim.x + threadIdx.x;
    if (i < BG * 256) g_adj1[i] = 0.f;
}

// ------- adj1[b,c,k] = sum_edges s[src,c]*s[dst,k]  (16 CTAs per graph) -------
__global__ void adj1_k(const int* __restrict__ src, const int* __restrict__ dst,
                       const float* __restrict__ s) {
    __shared__ float ss[NPG * 16];                   // 32 KB: full graph s
    int g = blockIdx.x >> 4;
    int part = blockIdx.x & 15;
    int t = threadIdx.x;                             // 256 threads
    for (int i = t; i < NPG * 16; i += 256) ss[i] = s[(size_t)g * NPG * 16 + i];
    __syncthreads();
    int c = t >> 4, k = t & 15;
    float acc = 0.f;
    int e0 = g * EPG + part * (EPG / 16);
    for (int j = 0; j < EPG / 16; j++) {
        int e = e0 + j;
        int a = src[e] & (NPG - 1);
        int b = dst[e] & (NPG - 1);
        acc = fmaf(ss[a * 16 + c], ss[b * 16 + k], acc);
    }
    atomicAdd(&g_adj1[g * 256 + t], acc);
}

// ---------------- dense head: one CTA per graph, everything in smem ----------
__global__ void dense_k(const float* __restrict__ x1, const float* __restrict__ adj,
                        const float* __restrict__ d1w, const float* __restrict__ d1b,
                        const float* __restrict__ d2w, const float* __restrict__ d2b,
                        const float* __restrict__ mw1, const float* __restrict__ mb1,
                        const float* __restrict__ mw2, const float* __restrict__ mb2,
                        float* __restrict__ out) {
    int g = blockIdx.x, t = threadIdx.x;             // 128 threads
    __shared__ float a[256], an[256], dv[16];
    __shared__ float xa[1024], tb[1024], xb[1024];
    __shared__ float gv[64], hid[128], red[128];
    for (int i = t; i < 256;  i += 128) a[i]  = adj[g * 256 + i];
    for (int i = t; i < 1024; i += 128) xa[i] = x1[g * 1024 + i];
    __syncthreads();
    if (t < 16) a[t * 16 + t] = 1.f;
    __syncthreads();
    if (t < 16) {
        float s = 0.f;
        for (int k = 0; k < 16; k++) s += a[t * 16 + k];
        dv[t] = rsqrtf(fmaxf(s, 1.f));
    }
    __syncthreads();
    for (int i = t; i < 256; i += 128) an[i] = dv[i >> 4] * a[i] * dv[i & 15];
    __syncthreads();
    // GCN layer 1
    for (int i = t; i < 1024; i += 128) {
        int c = i >> 6, f = i & 63;
        float acc = 0.f;
        for (int m = 0; m < 64; m++) acc = fmaf(xa[c * 64 + m], __ldg(d1w + m * 64 + f), acc);
        tb[i] = acc;
    }
    __syncthreads();
    for (int i = t; i < 1024; i += 128) {
        int c = i >> 6, f = i & 63;
        float acc = __ldg(d1b + f);
        for (int k = 0; k < 16; k++) acc = fmaf(an[c * 16 + k], tb[k * 64 + f], acc);
        xb[i] = fmaxf(acc, 0.f);
    }
    __syncthreads();
    // GCN layer 2
    for (int i = t; i < 1024; i += 128) {
        int c = i >> 6, f = i & 63;
        float acc = 0.f;
        for (int m = 0; m < 64; m++) acc = fmaf(xb[c * 64 + m], __ldg(d2w + m * 64 + f), acc);
        tb[i] = acc;
    }
    __syncthreads();
    for (int i = t; i < 1024; i += 128) {
        int c = i >> 6, f = i & 63;
        float acc = __ldg(d2b + f);
        for (int k = 0; k < 16; k++) acc = fmaf(an[c * 16 + k], tb[k * 64 + f], acc);
        xa[i] = fmaxf(acc, 0.f);
    }
    __syncthreads();
    // final pool (softmax over size-1 axis == all ones => plain sum over clusters)
    if (t < 64) {
        float s = 0.f;
        for (int c = 0; c < 16; c++) s += xa[c * 64 + t];
        gv[t] = s;
    }
    __syncthreads();
    // MLP head
    {
        float acc = __ldg(mb1 + t);
        for (int f = 0; f < 64; f++) acc = fmaf(gv[f], __ldg(mw1 + f * 128 + t), acc);
        hid[t] = fmaxf(acc, 0.f);
    }
    __syncthreads();
    red[t] = hid[t] * __ldg(mw2 + t);
    __syncthreads();
    for (int s = 64; s > 0; s >>= 1) {
        if (t < s) red[t] += red[t + s];
        __syncthreads();
    }
    if (t == 0) out[g] = red[0] + __ldg(mb2);
}

// ---------------- host ----------------
template<typename T>
static T* sym_addr(const void* sym) {
    void* p = nullptr;
    cudaGetSymbolAddress(&p, sym);
    return (T*)p;
}

extern "C" void kernel_launch(void* const* d_in, const int* in_sizes, int n_in,
                              void* d_out, int out_size) {
    const float* x    = (const float*)d_in[0];
    const int*   ei   = (const int*)d_in[1];
    const float* ea   = (const float*)d_in[2];
    // d_in[3] = batch (unused: equal-size graphs, blocked layout)
    const float* g1w1 = (const float*)d_in[4];
    const float* g1b1 = (const float*)d_in[5];
    const float* g1w2 = (const float*)d_in[6];
    const float* g1b2 = (const float*)d_in[7];
    const float* g2w1 = (const float*)d_in[8];
    const float* g2b1 = (const float*)d_in[9];
    const float* g2w2 = (const float*)d_in[10];
    const float* g2b2 = (const float*)d_in[11];
    const float* agw1 = (const float*)d_in[12];
    const float* agb1 = (const float*)d_in[13];
    const float* agw2 = (const float*)d_in[14];
    const float* agb2 = (const float*)d_in[15];
    const float* d1w  = (const float*)d_in[16];
    const float* d1b  = (const float*)d_in[17];
    const float* d2w  = (const float*)d_in[18];
    const float* d2b  = (const float*)d_in[19];
    // d_in[20], d_in[21] = ad_w, ad_b (provably unused: softmax over size-1 axis)
    const float* mw1  = (const float*)d_in[22];
    const float* mb1  = (const float*)d_in[23];
    const float* mw2  = (const float*)d_in[24];
    const float* mb2  = (const float*)d_in[25];
    float* out = (float*)d_out;

    const int* src = ei;
    const int* dst = ei + NE;

    float* pre  = sym_addr<float>(g_pre);
    float* h1   = sym_addr<float>(g_h1);
    float* h2   = sym_addr<float>(g_h2);
    float* sraw = sym_addr<float>(g_sraw);
    float* s    = sym_addr<float>(g_s);
    float* x1   = sym_addr<float>(g_x1);
    float* adj1 = sym_addr<float>(g_adj1);

    // CSR (dst is static per-run, but recompute every call: determinism rule)
    build_csr_k<<<BG, NPG>>>(dst);

    // conv1: pre = x @ g1_w1[0:16] + b1 ; agg with w1_edge = rows 16..23
    node_pre_k<16, 64><<<(NN * 64 + 255) / 256, 256>>>(x, g1w1, g1b1, pre);
    agg_k<64, true><<<NN / 8, 256>>>(src, ea, pre, g1w1 + 16 * 64, g1w2, g1b2, h1);

    // conv2
    node_pre_k<64, 64><<<(NN * 64 + 255) / 256, 256>>>(h1, g2w1, g2b1, pre);
    agg_k<64, true><<<NN / 8, 256>>>(src, ea, pre, g2w1 + 64 * 64, g2w2, g2b2, h2);

    // conv3 (assign): F=16, no trailing relu
    node_pre_k<64, 16><<<(NN * 16 + 255) / 256, 256>>>(h2, agw1, agb1, pre);
    agg_k<16, false><<<NN / 8, 256>>>(src, ea, pre, agw1 + 64 * 16, agw2, agb2, sraw);

    // s = softmax(softmax(sraw))  (reference applies softmax twice)
    softmax2_k<<<(NN + 255) / 256, 256>>>(sraw, s);

    // pooling: x1 = s^T h2 per graph ; adj1 = s^T A s via edge outer products
    x1_k<<<BG, 256>>>(s, h2, x1);
    zero_adj_k<<<16, 1024>>>();
    adj1_k<<<BG * 16, 256>>>(src, dst, s);

    // dense GCN x2 head -> output [64]
    dense_k<<<BG, 128>>>(x1, adj1, d1w, d1b, d2w, d2b, mw1, mb1, mw2, mb2, out);
}

// round 2
// speedup vs baseline: 1.5288x; 1.5288x over previous
#include <cuda_runtime.h>
#include <math.h>

// Problem constants
#define BG   64
#define NPG  512
#define DEG  32
#define EPG  (NPG*DEG)      // 16384 edges per graph
#define NE   (BG*EPG)       // 1048576
#define NN   (BG*NPG)       // 32768

// ---------------- device scratch (no runtime alloc allowed) ----------------
__device__ int2  g_perm2[NE];      // (edge index, src node) sorted by dst
__device__ int   g_off[NN];
__device__ int   g_cnt[NN];
__device__ float g_pre[NN*64];     // pre1
__device__ float g_preB[NN*64];    // pre2
__device__ float g_h2[NN*64];
__device__ float g_pre3[NN*16];
__device__ float g_s[NN*16];
__device__ float g_x1[BG*16*64];
__device__ float g_adj1[BG*16*16];

// ---------------- CSR build: counting sort by dst, parallel scan ----------------
__global__ void build_csr_k(const int* __restrict__ src, const int* __restrict__ dst) {
    __shared__ int scnt[NPG];
    __shared__ int wsum[16];
    int g = blockIdx.x, t = threadIdx.x;
    scnt[t] = 0;
    __syncthreads();
    int ebase = g * EPG, nbase = g * NPG;
    for (int e = t; e < EPG; e += NPG)
        atomicAdd(&scnt[dst[ebase + e] - nbase], 1);
    __syncthreads();
    int lane = t & 31, w = t >> 5;
    int v = scnt[t];
    int incl = v;
    #pragma unroll
    for (int d = 1; d < 32; d <<= 1) {
        int u = __shfl_up_sync(0xffffffffu, incl, d);
        if (lane >= d) incl += u;
    }
    if (lane == 31) wsum[w] = incl;
    __syncthreads();
    if (t == 0) {
        int run = 0;
        #pragma unroll
        for (int i = 0; i < 16; i++) { int x = wsum[i]; wsum[i] = run; run += x; }
    }
    __syncthreads();
    int excl = incl - v + wsum[w];
    g_off[nbase + t] = ebase + excl;
    g_cnt[nbase + t] = v;
    __syncthreads();
    scnt[t] = excl;                 // reuse as scatter cursor
    __syncthreads();
    for (int e = t; e < EPG; e += NPG) {
        int sv = src[ebase + e];
        int d = dst[ebase + e] - nbase;
        int p = atomicAdd(&scnt[d], 1);
        g_perm2[ebase + p] = make_int2(ebase + e, sv);
    }
}

// ---------------- pre1 = x @ g1_w1[0:16] + g1_b1  (vectorized, regs-hoisted) ----
__global__ void pre1_k(const float* __restrict__ x, const float* __restrict__ w,
                       const float* __restrict__ b, float* __restrict__ out) {
    int t = threadIdx.x, warp = t >> 5, lane = t & 31;
    int c0 = 2 * lane, c1 = c0 + 1;
    float wc0[16], wc1[16];
    #pragma unroll
    for (int k = 0; k < 16; k++) { wc0[k] = __ldg(w + k * 64 + c0); wc1[k] = __ldg(w + k * 64 + c1); }
    float b0 = __ldg(b + c0), b1 = __ldg(b + c1);
    int nbase = (blockIdx.x * 8 + warp) * 8;         // 8 nodes per warp
    for (int m = 0; m < 8; m++) {
        int n = nbase + m;
        const float4* row = (const float4*)(x + (size_t)n * 16);
        float4 r0 = __ldg(row + 0), r1 = __ldg(row + 1), r2 = __ldg(row + 2), r3 = __ldg(row + 3);
        float rv[16] = {r0.x, r0.y, r0.z, r0.w, r1.x, r1.y, r1.z, r1.w,
                        r2.x, r2.y, r2.z, r2.w, r3.x, r3.y, r3.z, r3.w};
        float d0 = b0, d1 = b1;
        #pragma unroll
        for (int k = 0; k < 16; k++) { d0 = fmaf(rv[k], wc0[k], d0); d1 = fmaf(rv[k], wc1[k], d1); }
        ((float2*)out)[(size_t)n * 32 + lane] = make_float2(d0, d1);
    }
}

// 8 fused FMAs of one edge's ea-vector against hoisted weight regs
#define EDGE_FMA(E0, E1, A0, A1)                                        \
    E0 = fmaf(A0.x, we0[0], E0); E1 = fmaf(A0.x, we1[0], E1);           \
    E0 = fmaf(A0.y, we0[1], E0); E1 = fmaf(A0.y, we1[1], E1);           \
    E0 = fmaf(A0.z, we0[2], E0); E1 = fmaf(A0.z, we1[2], E1);           \
    E0 = fmaf(A0.w, we0[3], E0); E1 = fmaf(A0.w, we1[3], E1);           \
    E0 = fmaf(A1.x, we0[4], E0); E1 = fmaf(A1.x, we1[4], E1);           \
    E0 = fmaf(A1.y, we0[5], E0); E1 = fmaf(A1.y, we1[5], E1);           \
    E0 = fmaf(A1.z, we0[6], E0); E1 = fmaf(A1.z, we1[6], E1);           \
    E0 = fmaf(A1.w, we0[7], E0); E1 = fmaf(A1.w, we1[7], E1);

// ------- fused aggregation (warp per node):
//   R = sum_e relu(pre[src] + ea@w1e); h = relu((R@w2 + cnt*b2)/max(cnt,1))
//   optional: write h; then pre_next = h @ wn + bn   (FN = 64 or 16)
template<int FN, bool WRITE_H>
__global__ void agg_k(const float* __restrict__ ea, const float* __restrict__ pre,
                      const float* __restrict__ w1e, const float* __restrict__ w2,
                      const float* __restrict__ b2, const float* __restrict__ wn,
                      const float* __restrict__ bn, float* __restrict__ outh,
                      float* __restrict__ outp) {
    __shared__ float sw2[64 * 64];
    __shared__ float sb2[64];
    __shared__ float swn[64 * FN];
    __shared__ float sbn[FN];
    __shared__ float rbuf[8][64];
    __shared__ float hbuf[8][64];
    int t = threadIdx.x;
    for (int i = t; i < 64 * 64; i += 256) sw2[i] = w2[i];
    if (t < 64) sb2[t] = b2[t];
    for (int i = t; i < 64 * FN; i += 256) swn[i] = wn[i];
    if (t < FN) sbn[t] = bn[t];
    int warp = t >> 5, lane = t & 31;
    int c0 = 2 * lane, c1 = c0 + 1;
    float we0[8], we1[8];
    #pragma unroll
    for (int k = 0; k < 8; k++) { we0[k] = __ldg(w1e + k * 64 + c0); we1[k] = __ldg(w1e + k * 64 + c1); }
    __syncthreads();

    int n = blockIdx.x * 8 + warp;
    int off = g_off[n], cnt = g_cnt[n];
    const int2* pp = g_perm2 + off;
    float accA0 = 0.f, accA1 = 0.f, accB0 = 0.f, accB1 = 0.f;
    int j = 0;
    for (; j + 2 <= cnt; j += 2) {
        int2 pA = __ldg(pp + j);
        int2 pB = __ldg(pp + j + 1);
        const float4* eaA = (const float4*)(ea + (size_t)pA.x * 8);
        const float4* eaB = (const float4*)(ea + (size_t)pB.x * 8);
        float4 a0 = __ldg(eaA), a1 = __ldg(eaA + 1);
        float4 b0 = __ldg(eaB), b1 = __ldg(eaB + 1);
        float2 gA = __ldg((const float2*)(pre + (size_t)pA.y * 64) + lane);
        float2 gB = __ldg((const float2*)(pre + (size_t)pB.y * 64) + lane);
        float eA0 = gA.x, eA1 = gA.y, eB0 = gB.x, eB1 = gB.y;
        EDGE_FMA(eA0, eA1, a0, a1)
        EDGE_FMA(eB0, eB1, b0, b1)
        accA0 += fmaxf(eA0, 0.f); accA1 += fmaxf(eA1, 0.f);
        accB0 += fmaxf(eB0, 0.f); accB1 += fmaxf(eB1, 0.f);
    }
    if (j < cnt) {
        int2 pA = __ldg(pp + j);
        const float4* eaA = (const float4*)(ea + (size_t)pA.x * 8);
        float4 a0 = __ldg(eaA), a1 = __ldg(eaA + 1);
        float2 gA = __ldg((const float2*)(pre + (size_t)pA.y * 64) + lane);
        float eA0 = gA.x, eA1 = gA.y;
        EDGE_FMA(eA0, eA1, a0, a1)
        accA0 += fmaxf(eA0, 0.f); accA1 += fmaxf(eA1, 0.f);
    }
    rbuf[warp][c0] = accA0 + accB0;
    rbuf[warp][c1] = accA1 + accB1;
    __syncwarp();

    float cntf = (float)cnt;
    float inv = 1.f / fmaxf(cntf, 1.f);
    float d0 = cntf * sb2[c0], d1 = cntf * sb2[c1];
    const float2* sw2v = (const float2*)sw2;
    #pragma unroll 8
    for (int k = 0; k < 64; k++) {
        float rk = rbuf[warp][k];
        float2 wv = sw2v[k * 32 + lane];
        d0 = fmaf(rk, wv.x, d0); d1 = fmaf(rk, wv.y, d1);
    }
    float h0 = fmaxf(d0 * inv, 0.f), h1 = fmaxf(d1 * inv, 0.f);
    if (WRITE_H) ((float2*)outh)[(size_t)n * 32 + lane] = make_float2(h0, h1);
    hbuf[warp][c0] = h0; hbuf[warp][c1] = h1;
    __syncwarp();
    if (FN == 64) {
        float p0 = sbn[c0], p1 = sbn[c1];
        const float2* swnv = (const float2*)swn;
        #pragma unroll 8
        for (int k = 0; k < 64; k++) {
            float hk = hbuf[warp][k];
            float2 wv = swnv[k * 32 + lane];
            p0 = fmaf(hk, wv.x, p0); p1 = fmaf(hk, wv.y, p1);
        }
        ((float2*)outp)[(size_t)n * 32 + lane] = make_float2(p0, p1);
    } else {    // FN == 16, lanes 0..7 compute 16 features
        if (lane < 8) {
            float p0 = sbn[c0], p1 = sbn[c1];
            const float2* swnv = (const float2*)swn;
            #pragma unroll 8
            for (int k = 0; k < 64; k++) {
                float hk = hbuf[warp][k];
                float2 wv = swnv[k * 8 + lane];
                p0 = fmaf(hk, wv.x, p0); p1 = fmaf(hk, wv.y, p1);
            }
            ((float2*)outp)[(size_t)n * 8 + lane] = make_float2(p0, p1);
        }
    }
}

// ------- assign conv (F=16) + fused double softmax; half-warp per edge -------
__global__ void agg3_k(const float* __restrict__ ea, const float* __restrict__ pre,
                       const float* __restrict__ w1e, const float* __restrict__ w2,
                       const float* __restrict__ b2, float* __restrict__ s_out) {
    __shared__ float sw2[256];
    __shared__ float sb2[16];
    __shared__ float rbuf[8][16];
    int t = threadIdx.x;
    if (t < 256) sw2[t] = w2[t];
    if (t < 16)  sb2[t] = b2[t];
    int warp = t >> 5, lane = t & 31, half = lane >> 4, f = lane & 15;
    float we[8];
    #pragma unroll
    for (int k = 0; k < 8; k++) we[k] = __ldg(w1e + k * 16 + f);
    __syncthreads();

    int n = blockIdx.x * 8 + warp;
    int off = g_off[n], cnt = g_cnt[n];
    const int2* pp = g_perm2 + off;
    float acc = 0.f;
    for (int j = half; j < cnt; j += 2) {
        int2 p = __ldg(pp + j);
        const float4* eap = (const float4*)(ea + (size_t)p.x * 8);
        float4 a0 = __ldg(eap), a1 = __ldg(eap + 1);
        float e0 = __ldg(pre + (size_t)p.y * 16 + f);
        e0 = fmaf(a0.x, we[0], e0); e0 = fmaf(a0.y, we[1], e0);
        e0 = fmaf(a0.z, we[2], e0); e0 = fmaf(a0.w, we[3], e0);
        e0 = fmaf(a1.x, we[4], e0); e0 = fmaf(a1.y, we[5], e0);
        e0 = fmaf(a1.z, we[6], e0); e0 = fmaf(a1.w, we[7], e0);
        acc += fmaxf(e0, 0.f);
    }
    acc += __shfl_xor_sync(0xffffffffu, acc, 16);
    if (half == 0) rbuf[warp][f] = acc;
    __syncwarp();
    float cntf = (float)cnt;
    float inv = 1.f / fmaxf(cntf, 1.f);
    float d = cntf * sb2[f];
    #pragma unroll
    for (int k = 0; k < 16; k++) d = fmaf(rbuf[warp][k], sw2[k * 16 + f], d);
    d *= inv;
    // double softmax over the 16-lane group (reference softmaxes twice)
    #pragma unroll
    for (int pass = 0; pass < 2; pass++) {
        float m = d;
        #pragma unroll
        for (int msk = 8; msk; msk >>= 1) m = fmaxf(m, __shfl_xor_sync(0xffffffffu, m, msk));
        float e = __expf(d - m);
        float ssum = e;
        #pragma unroll
        for (int msk = 8; msk; msk >>= 1) ssum += __shfl_xor_sync(0xffffffffu, ssum, msk);
        d = e / ssum;
    }
    if (half == 0) s_out[(size_t)n * 16 + f] = d;
}

// ---------------- zero x1 + adj1 accumulators ----------------
__global__ void zero_k() {
    int i = blockIdx.x * blockDim.x + threadIdx.x;
    if (i < BG * 1024) g_x1[i] = 0.f;
    if (i < BG * 256)  g_adj1[i] = 0.f;
}

// ---------------- x1[b,c,f] = sum_n s[b,n,c] * h[b,n,f]  (8-way split + atomics) ----
__global__ void x1_k(const float* __restrict__ s, const float* __restrict__ h) {
    int g = blockIdx.x >> 3, part = blockIdx.x & 7;
    int t = threadIdx.x, f = t & 63, cb = t >> 6;
    float acc[4] = {0.f, 0.f, 0.f, 0.f};
    const float* sg = s + (size_t)g * NPG * 16 + part * 64 * 16;
    const float* hg = h + (size_t)g * NPG * 64 + part * 64 * 64;
    for (int n = 0; n < 64; n++) {
        float hv = __ldg(hg + n * 64 + f);
        #pragma unroll
        for (int i = 0; i < 4; i++)
            acc[i] = fmaf(__ldg(sg + n * 16 + cb * 4 + i), hv, acc[i]);
    }
    #pragma unroll
    for (int i = 0; i < 4; i++)
        atomicAdd(&g_x1[g * 1024 + (cb * 4 + i) * 64 + f], acc[i]);
}

// ------- adj1[b,c,k] = sum_edges s[src,c]*s[dst,k]  (16 CTAs per graph) -------
__global__ void adj1_k(const int* __restrict__ src, const int* __restrict__ dst,
                       const float* __restrict__ s) {
    __shared__ float ss[NPG * 16];                   // 32 KB: full graph s
    int g = blockIdx.x >> 4, part = blockIdx.x & 15, t = threadIdx.x;
    for (int i = t; i < NPG * 16; i += 256) ss[i] = s[(size_t)g * NPG * 16 + i];
    __syncthreads();
    int c = t >> 4, k = t & 15;
    float a0 = 0.f, a1 = 0.f, a2 = 0.f, a3 = 0.f;
    int e0 = g * EPG + part * (EPG / 16);
    for (int j = 0; j < EPG / 16; j += 4) {
        int4 sv = __ldg((const int4*)(src + e0 + j));
        int4 dv = __ldg((const int4*)(dst + e0 + j));
        a0 = fmaf(ss[(sv.x & 511) * 16 + c], ss[(dv.x & 511) * 16 + k], a0);
        a1 = fmaf(ss[(sv.y & 511) * 16 + c], ss[(dv.y & 511) * 16 + k], a1);
        a2 = fmaf(ss[(sv.z & 511) * 16 + c], ss[(dv.z & 511) * 16 + k], a2);
        a3 = fmaf(ss[(sv.w & 511) * 16 + c], ss[(dv.w & 511) * 16 + k], a3);
    }
    atomicAdd(&g_adj1[g * 256 + t], (a0 + a1) + (a2 + a3));
}

// ---------------- dense head: one CTA per graph, everything in smem ----------
__global__ void dense_k(const float* __restrict__ x1, const float* __restrict__ adj,
                        const float* __restrict__ d1w, const float* __restrict__ d1b,
                        const float* __restrict__ d2w, const float* __restrict__ d2b,
                        const float* __restrict__ mw1, const float* __restrict__ mb1,
                        const float* __restrict__ mw2, const float* __restrict__ mb2,
                        float* __restrict__ out) {
    int g = blockIdx.x, t = threadIdx.x;             // 128 threads
    __shared__ float a[256], an[256], dv[16];
    __shared__ float xa[1024], tb[1024], xb[1024];
    __shared__ float gv[64], hid[128], red[128];
    for (int i = t; i < 256;  i += 128) a[i]  = adj[g * 256 + i];
    for (int i = t; i < 1024; i += 128) xa[i] = x1[g * 1024 + i];
    __syncthreads();
    if (t < 16) a[t * 16 + t] = 1.f;
    __syncthreads();
    if (t < 16) {
        float s = 0.f;
        for (int k = 0; k < 16; k++) s += a[t * 16 + k];
        dv[t] = rsqrtf(fmaxf(s, 1.f));
    }
    __syncthreads();
    for (int i = t; i < 256; i += 128) an[i] = dv[i >> 4] * a[i] * dv[i & 15];
    __syncthreads();
    // GCN layer 1
    for (int i = t; i < 1024; i += 128) {
        int c = i >> 6, f = i & 63;
        float acc = 0.f;
        for (int m = 0; m < 64; m++) acc = fmaf(xa[c * 64 + m], __ldg(d1w + m * 64 + f), acc);
        tb[i] = acc;
    }
    __syncthreads();
    for (int i = t; i < 1024; i += 128) {
        int c = i >> 6, f = i & 63;
        float acc = __ldg(d1b + f);
        for (int k = 0; k < 16; k++) acc = fmaf(an[c * 16 + k], tb[k * 64 + f], acc);
        xb[i] = fmaxf(acc, 0.f);
    }
    __syncthreads();
    // GCN layer 2
    for (int i = t; i < 1024; i += 128) {
        int c = i >> 6, f = i & 63;
        float acc = 0.f;
        for (int m = 0; m < 64; m++) acc = fmaf(xb[c * 64 + m], __ldg(d2w + m * 64 + f), acc);
        tb[i] = acc;
    }
    __syncthreads();
    for (int i = t; i < 1024; i += 128) {
        int c = i >> 6, f = i & 63;
        float acc = __ldg(d2b + f);
        for (int k = 0; k < 16; k++) acc = fmaf(an[c * 16 + k], tb[k * 64 + f], acc);
        xa[i] = fmaxf(acc, 0.f);
    }
    __syncthreads();
    // final pool: softmax over size-1 axis == ones => plain sum over clusters
    if (t < 64) {
        float s = 0.f;
        for (int c = 0; c < 16; c++) s += xa[c * 64 + t];
        gv[t] = s;
    }
    __syncthreads();
    {
        float acc = __ldg(mb1 + t);
        for (int f = 0; f < 64; f++) acc = fmaf(gv[f], __ldg(mw1 + f * 128 + t), acc);
        hid[t] = fmaxf(acc, 0.f);
    }
    __syncthreads();
    red[t] = hid[t] * __ldg(mw2 + t);
    __syncthreads();
    for (int s = 64; s > 0; s >>= 1) {
        if (t < s) red[t] += red[t + s];
        __syncthreads();
    }
    if (t == 0) out[g] = red[0] + __ldg(mb2);
}

// ---------------- host ----------------
template<typename T>
static T* sym_addr(const void* sym) {
    void* p = nullptr;
    cudaGetSymbolAddress(&p, sym);
    return (T*)p;
}

extern "C" void kernel_launch(void* const* d_in, const int* in_sizes, int n_in,
                              void* d_out, int out_size) {
    const float* x    = (const float*)d_in[0];
    const int*   ei   = (const int*)d_in[1];
    const float* ea   = (const float*)d_in[2];
    const float* g1w1 = (const float*)d_in[4];
    const float* g1b1 = (const float*)d_in[5];
    const float* g1w2 = (const float*)d_in[6];
    const float* g1b2 = (const float*)d_in[7];
    const float* g2w1 = (const float*)d_in[8];
    const float* g2b1 = (const float*)d_in[9];
    const float* g2w2 = (const float*)d_in[10];
    const float* g2b2 = (const float*)d_in[11];
    const float* agw1 = (const float*)d_in[12];
    const float* agb1 = (const float*)d_in[13];
    const float* agw2 = (const float*)d_in[14];
    const float* agb2 = (const float*)d_in[15];
    const float* d1w  = (const float*)d_in[16];
    const float* d1b  = (const float*)d_in[17];
    const float* d2w  = (const float*)d_in[18];
    const float* d2b  = (const float*)d_in[19];
    // d_in[20..21] = ad_w, ad_b (dead: softmax over size-1 axis => ones)
    const float* mw1  = (const float*)d_in[22];
    const float* mb1  = (const float*)d_in[23];
    const float* mw2  = (const float*)d_in[24];
    const float* mb2  = (const float*)d_in[25];
    float* out = (float*)d_out;

    const int* src = ei;
    const int* dst = ei + NE;

    float* pre  = sym_addr<float>(g_pre);
    float* preB = sym_addr<float>(g_preB);
    float* h2   = sym_addr<float>(g_h2);
    float* pre3 = sym_addr<float>(g_pre3);
    float* s    = sym_addr<float>(g_s);
    float* x1   = sym_addr<float>(g_x1);
    float* adj1 = sym_addr<float>(g_adj1);

    build_csr_k<<<BG, NPG>>>(src, dst);

    // conv1 node pre: pre = x @ g1_w1[0:16] + g1_b1
    pre1_k<<<NN / 64, 256>>>(x, g1w1, g1b1, pre);

    // conv1 agg + fused conv2 node-pre (h1 never materialized)
    agg_k<64, false><<<NN / 8, 256>>>(ea, pre, g1w1 + 16 * 64, g1w2, g1b2,
                                      g2w1, g2b1, nullptr, preB);

    // conv2 agg: writes h2, fused assign node-pre (64 -> 16)
    agg_k<16, true><<<NN / 8, 256>>>(ea, preB, g2w1 + 64 * 64, g2w2, g2b2,
                                     agw1, agb1, h2, pre3);

    // assign conv (16 feats) + fused double softmax
    agg3_k<<<NN / 8, 256>>>(ea, pre3, agw1 + 64 * 16, agw2, agb2, s);

    // pooling
    zero_k<<<256, 256>>>();
    x1_k<<<BG * 8, 256>>>(s, h2);
    adj1_k<<<BG * 16, 256>>>(src, dst, s);

    // dense GCN head -> output [64]
    dense_k<<<BG, 128>>>(x1, adj1, d1w, d1b, d2w, d2b, mw1, mb1, mw2, mb2, out);
}

// round 3
// speedup vs baseline: 1.5330x; 1.0028x over previous
#include <cuda_runtime.h>
#include <math.h>

// Problem constants
#define BG   64
#define NPG  512
#define DEG  32
#define EPG  (NPG*DEG)      // 16384 edges per graph
#define NE   (BG*EPG)       // 1048576
#define NN   (BG*NPG)       // 32768

// ---------------- device scratch (no runtime alloc allowed) ----------------
__device__ int2  g_perm2[NE];      // (edge index, src node) sorted by dst
__device__ int   g_off[NN];
__device__ int   g_cnt[NN];
__device__ float g_pre[NN*64];     // pre1
__device__ float g_preB[NN*64];    // pre2
__device__ float g_h2[NN*64];
__device__ float g_pre3[NN*16];
__device__ float g_s[NN*16];
__device__ float g_x1[BG*16*64];
__device__ float g_adj1[BG*16*16];

// ---------------- CSR build: counting sort by dst, parallel scan ----------------
__global__ void build_csr_k(const int* __restrict__ src, const int* __restrict__ dst) {
    __shared__ int scnt[NPG];
    __shared__ int wsum[16];
    int g = blockIdx.x, t = threadIdx.x;
    scnt[t] = 0;
    __syncthreads();
    int ebase = g * EPG, nbase = g * NPG;
    for (int e = t; e < EPG; e += NPG)
        atomicAdd(&scnt[dst[ebase + e] - nbase], 1);
    __syncthreads();
    int lane = t & 31, w = t >> 5;
    int v = scnt[t];
    int incl = v;
    #pragma unroll
    for (int d = 1; d < 32; d <<= 1) {
        int u = __shfl_up_sync(0xffffffffu, incl, d);
        if (lane >= d) incl += u;
    }
    if (lane == 31) wsum[w] = incl;
    __syncthreads();
    if (t == 0) {
        int run = 0;
        #pragma unroll
        for (int i = 0; i < 16; i++) { int x = wsum[i]; wsum[i] = run; run += x; }
    }
    __syncthreads();
    int excl = incl - v + wsum[w];
    g_off[nbase + t] = ebase + excl;
    g_cnt[nbase + t] = v;
    __syncthreads();
    scnt[t] = excl;                 // reuse as scatter cursor
    __syncthreads();
    for (int e = t; e < EPG; e += NPG) {
        int sv = src[ebase + e];
        int d = dst[ebase + e] - nbase;
        int p = atomicAdd(&scnt[d], 1);
        g_perm2[ebase + p] = make_int2(ebase + e, sv);
    }
}

// ---------------- pre1 = x @ g1_w1[0:16] + g1_b1  (vectorized, regs-hoisted) ----
__global__ void pre1_k(const float* __restrict__ x, const float* __restrict__ w,
                       const float* __restrict__ b, float* __restrict__ out) {
    int t = threadIdx.x, warp = t >> 5, lane = t & 31;
    int c0 = 2 * lane, c1 = c0 + 1;
    float wc0[16], wc1[16];
    #pragma unroll
    for (int k = 0; k < 16; k++) { wc0[k] = __ldg(w + k * 64 + c0); wc1[k] = __ldg(w + k * 64 + c1); }
    float b0 = __ldg(b + c0), b1 = __ldg(b + c1);
    int nbase = (blockIdx.x * 8 + warp) * 8;         // 8 nodes per warp
    for (int m = 0; m < 8; m++) {
        int n = nbase + m;
        const float4* row = (const float4*)(x + (size_t)n * 16);
        float4 r0 = __ldg(row + 0), r1 = __ldg(row + 1), r2 = __ldg(row + 2), r3 = __ldg(row + 3);
        float rv[16] = {r0.x, r0.y, r0.z, r0.w, r1.x, r1.y, r1.z, r1.w,
                        r2.x, r2.y, r2.z, r2.w, r3.x, r3.y, r3.z, r3.w};
        float d0 = b0, d1 = b1;
        #pragma unroll
        for (int k = 0; k < 16; k++) { d0 = fmaf(rv[k], wc0[k], d0); d1 = fmaf(rv[k], wc1[k], d1); }
        ((float2*)out)[(size_t)n * 32 + lane] = make_float2(d0, d1);
    }
}

// 8 fused FMAs of one edge's ea-vector against hoisted weight regs
#define EDGE_FMA(E0, E1, A0, A1)                                        \
    E0 = fmaf(A0.x, we0[0], E0); E1 = fmaf(A0.x, we1[0], E1);           \
    E0 = fmaf(A0.y, we0[1], E0); E1 = fmaf(A0.y, we1[1], E1);           \
    E0 = fmaf(A0.z, we0[2], E0); E1 = fmaf(A0.z, we1[2], E1);           \
    E0 = fmaf(A0.w, we0[3], E0); E1 = fmaf(A0.w, we1[3], E1);           \
    E0 = fmaf(A1.x, we0[4], E0); E1 = fmaf(A1.x, we1[4], E1);           \
    E0 = fmaf(A1.y, we0[5], E0); E1 = fmaf(A1.y, we1[5], E1);           \
    E0 = fmaf(A1.z, we0[6], E0); E1 = fmaf(A1.z, we1[6], E1);           \
    E0 = fmaf(A1.w, we0[7], E0); E1 = fmaf(A1.w, we1[7], E1);

// ------- fused aggregation (warp per node):
//   R = sum_e relu(pre[src] + ea@w1e); h = relu((R@w2 + cnt*b2)/max(cnt,1))
//   optional: write h; then pre_next = h @ wn + bn   (FN = 64 or 16)
template<int FN, bool WRITE_H>
__global__ void agg_k(const float* __restrict__ ea, const float* __restrict__ pre,
                      const float* __restrict__ w1e, const float* __restrict__ w2,
                      const float* __restrict__ b2, const float* __restrict__ wn,
                      const float* __restrict__ bn, float* __restrict__ outh,
                      float* __restrict__ outp) {
    __shared__ float sw2[64 * 64];
    __shared__ float sb2[64];
    __shared__ float swn[64 * FN];
    __shared__ float sbn[FN];
    __shared__ float rbuf[8][64];
    __shared__ float hbuf[8][64];
    int t = threadIdx.x;
    for (int i = t; i < 64 * 64; i += 256) sw2[i] = w2[i];
    if (t < 64) sb2[t] = b2[t];
    for (int i = t; i < 64 * FN; i += 256) swn[i] = wn[i];
    if (t < FN) sbn[t] = bn[t];
    int warp = t >> 5, lane = t & 31;
    int c0 = 2 * lane, c1 = c0 + 1;
    float we0[8], we1[8];
    #pragma unroll
    for (int k = 0; k < 8; k++) { we0[k] = __ldg(w1e + k * 64 + c0); we1[k] = __ldg(w1e + k * 64 + c1); }
    __syncthreads();

    int n = blockIdx.x * 8 + warp;
    int off = g_off[n], cnt = g_cnt[n];
    const int2* pp = g_perm2 + off;
    float accA0 = 0.f, accA1 = 0.f, accB0 = 0.f, accB1 = 0.f;
    int j = 0;
    for (; j + 2 <= cnt; j += 2) {
        int2 pA = __ldg(pp + j);
        int2 pB = __ldg(pp + j + 1);
        const float4* eaA = (const float4*)(ea + (size_t)pA.x * 8);
        const float4* eaB = (const float4*)(ea + (size_t)pB.x * 8);
        float4 a0 = __ldg(eaA), a1 = __ldg(eaA + 1);
        float4 b0 = __ldg(eaB), b1 = __ldg(eaB + 1);
        float2 gA = __ldg((const float2*)(pre + (size_t)pA.y * 64) + lane);
        float2 gB = __ldg((const float2*)(pre + (size_t)pB.y * 64) + lane);
        float eA0 = gA.x, eA1 = gA.y, eB0 = gB.x, eB1 = gB.y;
        EDGE_FMA(eA0, eA1, a0, a1)
        EDGE_FMA(eB0, eB1, b0, b1)
        accA0 += fmaxf(eA0, 0.f); accA1 += fmaxf(eA1, 0.f);
        accB0 += fmaxf(eB0, 0.f); accB1 += fmaxf(eB1, 0.f);
    }
    if (j < cnt) {
        int2 pA = __ldg(pp + j);
        const float4* eaA = (const float4*)(ea + (size_t)pA.x * 8);
        float4 a0 = __ldg(eaA), a1 = __ldg(eaA + 1);
        float2 gA = __ldg((const float2*)(pre + (size_t)pA.y * 64) + lane);
        float eA0 = gA.x, eA1 = gA.y;
        EDGE_FMA(eA0, eA1, a0, a1)
        accA0 += fmaxf(eA0, 0.f); accA1 += fmaxf(eA1, 0.f);
    }
    rbuf[warp][c0] = accA0 + accB0;
    rbuf[warp][c1] = accA1 + accB1;
    __syncwarp();

    float cntf = (float)cnt;
    float inv = 1.f / fmaxf(cntf, 1.f);
    float d0 = cntf * sb2[c0], d1 = cntf * sb2[c1];
    const float2* sw2v = (const float2*)sw2;
    #pragma unroll 8
    for (int k = 0; k < 64; k++) {
        float rk = rbuf[warp][k];
        float2 wv = sw2v[k * 32 + lane];
        d0 = fmaf(rk, wv.x, d0); d1 = fmaf(rk, wv.y, d1);
    }
    float h0 = fmaxf(d0 * inv, 0.f), h1 = fmaxf(d1 * inv, 0.f);
    if (WRITE_H) ((float2*)outh)[(size_t)n * 32 + lane] = make_float2(h0, h1);
    hbuf[warp][c0] = h0; hbuf[warp][c1] = h1;
    __syncwarp();
    if (FN == 64) {
        float p0 = sbn[c0], p1 = sbn[c1];
        const float2* swnv = (const float2*)swn;
        #pragma unroll 8
        for (int k = 0; k < 64; k++) {
            float hk = hbuf[warp][k];
            float2 wv = swnv[k * 32 + lane];
            p0 = fmaf(hk, wv.x, p0); p1 = fmaf(hk, wv.y, p1);
        }
        ((float2*)outp)[(size_t)n * 32 + lane] = make_float2(p0, p1);
    } else {    // FN == 16, lanes 0..7 compute 16 features
        if (lane < 8) {
            float p0 = sbn[c0], p1 = sbn[c1];
            const float2* swnv = (const float2*)swn;
            #pragma unroll 8
            for (int k = 0; k < 64; k++) {
                float hk = hbuf[warp][k];
                float2 wv = swnv[k * 8 + lane];
                p0 = fmaf(hk, wv.x, p0); p1 = fmaf(hk, wv.y, p1);
            }
            ((float2*)outp)[(size_t)n * 8 + lane] = make_float2(p0, p1);
        }
    }
}

// ------- assign conv (F=16) + fused double softmax; half-warp per edge -------
__global__ void agg3_k(const float* __restrict__ ea, const float* __restrict__ pre,
                       const float* __restrict__ w1e, const float* __restrict__ w2,
                       const float* __restrict__ b2, float* __restrict__ s_out) {
    __shared__ float sw2[256];
    __shared__ float sb2[16];
    __shared__ float rbuf[8][16];
    int t = threadIdx.x;
    if (t < 256) sw2[t] = w2[t];
    if (t < 16)  sb2[t] = b2[t];
    int warp = t >> 5, lane = t & 31, half = lane >> 4, f = lane & 15;
    float we[8];
    #pragma unroll
    for (int k = 0; k < 8; k++) we[k] = __ldg(w1e + k * 16 + f);
    __syncthreads();

    int n = blockIdx.x * 8 + warp;
    int off = g_off[n], cnt = g_cnt[n];
    const int2* pp = g_perm2 + off;
    float acc = 0.f;
    for (int j = half; j < cnt; j += 2) {
        int2 p = __ldg(pp + j);
        const float4* eap = (const float4*)(ea + (size_t)p.x * 8);
        float4 a0 = __ldg(eap), a1 = __ldg(eap + 1);
        float e0 = __ldg(pre + (size_t)p.y * 16 + f);
        e0 = fmaf(a0.x, we[0], e0); e0 = fmaf(a0.y, we[1], e0);
        e0 = fmaf(a0.z, we[2], e0); e0 = fmaf(a0.w, we[3], e0);
        e0 = fmaf(a1.x, we[4], e0); e0 = fmaf(a1.y, we[5], e0);
        e0 = fmaf(a1.z, we[6], e0); e0 = fmaf(a1.w, we[7], e0);
        acc += fmaxf(e0, 0.f);
    }
    acc += __shfl_xor_sync(0xffffffffu, acc, 16);
    if (half == 0) rbuf[warp][f] = acc;
    __syncwarp();
    float cntf = (float)cnt;
    float inv = 1.f / fmaxf(cntf, 1.f);
    float d = cntf * sb2[f];
    #pragma unroll
    for (int k = 0; k < 16; k++) d = fmaf(rbuf[warp][k], sw2[k * 16 + f], d);
    d *= inv;
    // double softmax over the 16-lane group (reference softmaxes twice)
    #pragma unroll
    for (int pass = 0; pass < 2; pass++) {
        float m = d;
        #pragma unroll
        for (int msk = 8; msk; msk >>= 1) m = fmaxf(m, __shfl_xor_sync(0xffffffffu, m, msk));
        float e = __expf(d - m);
        float ssum = e;
        #pragma unroll
        for (int msk = 8; msk; msk >>= 1) ssum += __shfl_xor_sync(0xffffffffu, ssum, msk);
        d = e / ssum;
    }
    if (half == 0) s_out[(size_t)n * 16 + f] = d;
}

// ---------------- zero x1 + adj1 accumulators ----------------
__global__ void zero_k() {
    int i = blockIdx.x * blockDim.x + threadIdx.x;
    if (i < BG * 1024) g_x1[i] = 0.f;
    if (i < BG * 256)  g_adj1[i] = 0.f;
}

// ---------------- x1[b,c,f] = sum_n s[b,n,c] * h[b,n,f]  (8-way split + atomics) ----
__global__ void x1_k(const float* __restrict__ s, const float* __restrict__ h) {
    int g = blockIdx.x >> 3, part = blockIdx.x & 7;
    int t = threadIdx.x, f = t & 63, cb = t >> 6;
    float acc[4] = {0.f, 0.f, 0.f, 0.f};
    const float* sg = s + (size_t)g * NPG * 16 + part * 64 * 16;
    const float* hg = h + (size_t)g * NPG * 64 + part * 64 * 64;
    for (int n = 0; n < 64; n++) {
        float hv = __ldg(hg + n * 64 + f);
        #pragma unroll
        for (int i = 0; i < 4; i++)
            acc[i] = fmaf(__ldg(sg + n * 16 + cb * 4 + i), hv, acc[i]);
    }
    #pragma unroll
    for (int i = 0; i < 4; i++)
        atomicAdd(&g_x1[g * 1024 + (cb * 4 + i) * 64 + f], acc[i]);
}

// ------- adj1[b,c,k] = sum_edges s[src,c]*s[dst,k]  (16 CTAs per graph) -------
__global__ void adj1_k(const int* __restrict__ src, const int* __restrict__ dst,
                       const float* __restrict__ s) {
    __shared__ float ss[NPG * 16];                   // 32 KB: full graph s
    int g = blockIdx.x >> 4, part = blockIdx.x & 15, t = threadIdx.x;
    for (int i = t; i < NPG * 16; i += 256) ss[i] = s[(size_t)g * NPG * 16 + i];
    __syncthreads();
    int c = t >> 4, k = t & 15;
    float a0 = 0.f, a1 = 0.f, a2 = 0.f, a3 = 0.f;
    int e0 = g * EPG + part * (EPG / 16);
    for (int j = 0; j < EPG / 16; j += 4) {
        int4 sv = __ldg((const int4*)(src + e0 + j));
        int4 dv = __ldg((const int4*)(dst + e0 + j));
        a0 = fmaf(ss[(sv.x & 511) * 16 + c], ss[(dv.x & 511) * 16 + k], a0);
        a1 = fmaf(ss[(sv.y & 511) * 16 + c], ss[(dv.y & 511) * 16 + k], a1);
        a2 = fmaf(ss[(sv.z & 511) * 16 + c], ss[(dv.z & 511) * 16 + k], a2);
        a3 = fmaf(ss[(sv.w & 511) * 16 + c], ss[(dv.w & 511) * 16 + k], a3);
    }
    atomicAdd(&g_adj1[g * 256 + t], (a0 + a1) + (a2 + a3));
}

// ---------------- dense head: one CTA per graph, everything in smem ----------
__global__ void dense_k(const float* __restrict__ x1, const float* __restrict__ adj,
                        const float* __restrict__ d1w, const float* __restrict__ d1b,
                        const float* __restrict__ d2w, const float* __restrict__ d2b,
                        const float* __restrict__ mw1, const float* __restrict__ mb1,
                        const float* __restrict__ mw2, const float* __restrict__ mb2,
                        float* __restrict__ out) {
    int g = blockIdx.x, t = threadIdx.x;             // 128 threads
    __shared__ float a[256], an[256], dv[16];
    __shared__ float xa[1024], tb[1024], xb[1024];
    __shared__ float gv[64], hid[128], red[128];
    for (int i = t; i < 256;  i += 128) a[i]  = adj[g * 256 + i];
    for (int i = t; i < 1024; i += 128) xa[i] = x1[g * 1024 + i];
    __syncthreads();
    if (t < 16) a[t * 16 + t] = 1.f;
    __syncthreads();
    if (t < 16) {
        float s = 0.f;
        for (int k = 0; k < 16; k++) s += a[t * 16 + k];
        dv[t] = rsqrtf(fmaxf(s, 1.f));
    }
    __syncthreads();
    for (int i = t; i < 256; i += 128) an[i] = dv[i >> 4] * a[i] * dv[i & 15];
    __syncthreads();
    // GCN layer 1
    for (int i = t; i < 1024; i += 128) {
        int c = i >> 6, f = i & 63;
        float acc = 0.f;
        for (int m = 0; m < 64; m++) acc = fmaf(xa[c * 64 + m], __ldg(d1w + m * 64 + f), acc);
        tb[i] = acc;
    }
    __syncthreads();
    for (int i = t; i < 1024; i += 128) {
        int c = i >> 6, f = i & 63;
        float acc = __ldg(d1b + f);
        for (int k = 0; k < 16; k++) acc = fmaf(an[c * 16 + k], tb[k * 64 + f], acc);
        xb[i] = fmaxf(acc, 0.f);
    }
    __syncthreads();
    // GCN layer 2
    for (int i = t; i < 1024; i += 128) {
        int c = i >> 6, f = i & 63;
        float acc = 0.f;
        for (int m = 0; m < 64; m++) acc = fmaf(xb[c * 64 + m], __ldg(d2w + m * 64 + f), acc);
        tb[i] = acc;
    }
    __syncthreads();
    for (int i = t; i < 1024; i += 128) {
        int c = i >> 6, f = i & 63;
        float acc = __ldg(d2b + f);
        for (int k = 0; k < 16; k++) acc = fmaf(an[c * 16 + k], tb[k * 64 + f], acc);
        xa[i] = fmaxf(acc, 0.f);
    }
    __syncthreads();
    // final pool: softmax over size-1 axis == ones => plain sum over clusters
    if (t < 64) {
        float s = 0.f;
        for (int c = 0; c < 16; c++) s += xa[c * 64 + t];
        gv[t] = s;
    }
    __syncthreads();
    {
        float acc = __ldg(mb1 + t);
        for (int f = 0; f < 64; f++) acc = fmaf(gv[f], __ldg(mw1 + f * 128 + t), acc);
        hid[t] = fmaxf(acc, 0.f);
    }
    __syncthreads();
    red[t] = hid[t] * __ldg(mw2 + t);
    __syncthreads();
    for (int s = 64; s > 0; s >>= 1) {
        if (t < s) red[t] += red[t + s];
        __syncthreads();
    }
    if (t == 0) out[g] = red[0] + __ldg(mb2);
}

// ---------------- host ----------------
template<typename T>
static T* sym_addr(const void* sym) {
    void* p = nullptr;
    cudaGetSymbolAddress(&p, sym);
    return (T*)p;
}

extern "C" void kernel_launch(void* const* d_in, const int* in_sizes, int n_in,
                              void* d_out, int out_size) {
    const float* x    = (const float*)d_in[0];
    const int*   ei   = (const int*)d_in[1];
    const float* ea   = (const float*)d_in[2];
    const float* g1w1 = (const float*)d_in[4];
    const float* g1b1 = (const float*)d_in[5];
    const float* g1w2 = (const float*)d_in[6];
    const float* g1b2 = (const float*)d_in[7];
    const float* g2w1 = (const float*)d_in[8];
    const float* g2b1 = (const float*)d_in[9];
    const float* g2w2 = (const float*)d_in[10];
    const float* g2b2 = (const float*)d_in[11];
    const float* agw1 = (const float*)d_in[12];
    const float* agb1 = (const float*)d_in[13];
    const float* agw2 = (const float*)d_in[14];
    const float* agb2 = (const float*)d_in[15];
    const float* d1w  = (const float*)d_in[16];
    const float* d1b  = (const float*)d_in[17];
    const float* d2w  = (const float*)d_in[18];
    const float* d2b  = (const float*)d_in[19];
    // d_in[20..21] = ad_w, ad_b (dead: softmax over size-1 axis => ones)
    const float* mw1  = (const float*)d_in[22];
    const float* mb1  = (const float*)d_in[23];
    const float* mw2  = (const float*)d_in[24];
    const float* mb2  = (const float*)d_in[25];
    float* out = (float*)d_out;

    const int* src = ei;
    const int* dst = ei + NE;

    float* pre  = sym_addr<float>(g_pre);
    float* preB = sym_addr<float>(g_preB);
    float* h2   = sym_addr<float>(g_h2);
    float* pre3 = sym_addr<float>(g_pre3);
    float* s    = sym_addr<float>(g_s);
    float* x1   = sym_addr<float>(g_x1);
    float* adj1 = sym_addr<float>(g_adj1);

    build_csr_k<<<BG, NPG>>>(src, dst);

    // conv1 node pre: pre = x @ g1_w1[0:16] + g1_b1
    pre1_k<<<NN / 64, 256>>>(x, g1w1, g1b1, pre);

    // conv1 agg + fused conv2 node-pre (h1 never materialized)
    agg_k<64, false><<<NN / 8, 256>>>(ea, pre, g1w1 + 16 * 64, g1w2, g1b2,
                                      g2w1, g2b1, nullptr, preB);

    // conv2 agg: writes h2, fused assign node-pre (64 -> 16)
    agg_k<16, true><<<NN / 8, 256>>>(ea, preB, g2w1 + 64 * 64, g2w2, g2b2,
                                     agw1, agb1, h2, pre3);

    // assign conv (16 feats) + fused double softmax
    agg3_k<<<NN / 8, 256>>>(ea, pre3, agw1 + 64 * 16, agw2, agb2, s);

    // pooling
    zero_k<<<256, 256>>>();
    x1_k<<<BG * 8, 256>>>(s, h2);
    adj1_k<<<BG * 16, 256>>>(src, dst, s);

    // dense GCN head -> output [64]
    dense_k<<<BG, 128>>>(x1, adj1, d1w, d1b, d2w, d2b, mw1, mb1, mw2, mb2, out);
}